// round 3
// baseline (speedup 1.0000x reference)
#include <cuda_runtime.h>
#include <math.h>

// Problem constants
#define NB   32
#define CC   256
#define HH   56
#define WW   56
#define HWP  3136      // 56*56
#define CHW  802816    // 256*3136

// GEMM tiling for the dilated conv (implicit GEMM over 25 taps)
#define BM 128   // output channels per block
#define BN 64    // pixels per block (3136 = 49*64, exact)
#define BK 16    // ci slice

// Scratch (device globals; no allocation)
__device__ float g_Wre[25 * 256 * 256];   // [tap][ci][co]
__device__ float g_t1[NB * CC * HH];      // max over W
__device__ float g_t9[NB * HH * WW];      // softmax weights

// ---------------------------------------------------------------------------
// 1) Weight re-layout: w7[co, ci*25 + tap] -> Wre[(tap*256+ci)*256 + co]
// ---------------------------------------------------------------------------
__global__ void transpose_w_kernel(const float* __restrict__ w7) {
    int idx = blockIdx.x * blockDim.x + threadIdx.x;   // 25*256*256 total, exact grid
    int co  = idx & 255;
    int ci  = (idx >> 8) & 255;
    int tap = idx >> 16;
    g_Wre[idx] = w7[co * 6400 + ci * 25 + tap];
}

// ---------------------------------------------------------------------------
// 2) t1 = max over W. One warp per (n,c,h) row of 56.
// ---------------------------------------------------------------------------
__global__ void rowmax_kernel(const float* __restrict__ x) {
    int row  = blockIdx.x * 4 + (threadIdx.x >> 5);    // 458752 rows, exact
    int lane = threadIdx.x & 31;
    const float* xr = x + row * 56;
    float m = xr[lane];
    if (lane < 24) m = fmaxf(m, xr[lane + 32]);
    #pragma unroll
    for (int o = 16; o > 0; o >>= 1)
        m = fmaxf(m, __shfl_xor_sync(0xffffffffu, m, o));
    if (lane == 0) g_t1[row] = m;
}

// ---------------------------------------------------------------------------
// 3) t6[n,h,w] = sum_c tanh(relu(x)) * w6[c]; t9 = softmax_w(t6)
//    One block per (n,h); thread t owns column w=t.
// ---------------------------------------------------------------------------
__global__ void softmax_kernel(const float* __restrict__ x,
                               const float* __restrict__ w6) {
    __shared__ float w6s[256];
    __shared__ float red[64];
    int n = blockIdx.y, h = blockIdx.x;
    int t = threadIdx.x;                                // 64 threads
    for (int c = t; c < 256; c += 64) w6s[c] = w6[c];
    __syncthreads();

    float acc = 0.f;
    if (t < 56) {
        const float* xp = x + (n * 256 * 56 + h) * 56 + t;
        #pragma unroll 4
        for (int c = 0; c < 256; c++) {
            float v = xp[c * HWP];
            float r = fmaxf(v, 0.f);
            float th;
            asm("tanh.approx.f32 %0, %1;" : "=f"(th) : "f"(r));
            acc += th * w6s[c];
        }
    }
    red[t] = (t < 56) ? acc : -INFINITY;
    __syncthreads();
    #pragma unroll
    for (int s = 32; s > 0; s >>= 1) {
        if (t < s) red[t] = fmaxf(red[t], red[t + s]);
        __syncthreads();
    }
    float mx = red[0];
    __syncthreads();
    float e = (t < 56) ? expf(acc - mx) : 0.f;
    red[t] = e;
    __syncthreads();
    #pragma unroll
    for (int s = 32; s > 0; s >>= 1) {
        if (t < s) red[t] += red[t + s];
        __syncthreads();
    }
    float inv = 1.0f / red[0];
    if (t < 56) g_t9[(n * 56 + h) * 56 + t] = e * inv;
}

// ---------------------------------------------------------------------------
// 4) Dilated conv as 25 shifted GEMMs + fused epilogue:
//    out[n,co,h,w] = t1[n,co,h] - ( t9[n,h,w]*x[n,co,(h-2)%56,w] + x[n,co,h,w]*t7 )
// ---------------------------------------------------------------------------
__global__ __launch_bounds__(256) void conv_fused_kernel(const float* __restrict__ x,
                                                         float* __restrict__ out) {
    __shared__ __align__(16) float As[BK][BM];   // weights [k][co]
    __shared__ __align__(16) float Bs[BK][BN];   // inputs  [k][p]

    const int n   = blockIdx.z;
    const int p0  = blockIdx.x * BN;
    const int co0 = blockIdx.y * BM;
    const int tid = threadIdx.x;

    const float* xn = x + n * CHW;

    // B-load mapping: 256 thr -> p in [0,64), k-row in [0,4); 4 loads each
    const int pb = tid & 63;
    const int kb = tid >> 6;
    const int pg = p0 + pb;
    const int ph = pg / 56;
    const int pw = pg - ph * 56;

    // A-load mapping: co in [0,128), k-row in [0,2); 8 loads each
    const int ca = tid & 127;
    const int ka = tid >> 7;

    // compute mapping: 16x16 thread grid, 8x4 micro-tile
    const int tr = tid >> 4;
    const int tc = tid & 15;

    float acc[8][4];
    #pragma unroll
    for (int i = 0; i < 8; i++)
        #pragma unroll
        for (int j = 0; j < 4; j++) acc[i][j] = 0.f;

    for (int tap = 0; tap < 25; tap++) {
        const int dh = (tap / 5) * 3 - 6;
        const int dw = (tap % 5) * 3 - 6;
        const int ih = ph + dh, iw = pw + dw;
        const bool valid = ((unsigned)ih < 56u) && ((unsigned)iw < 56u);
        const float* bsrc = xn + ih * 56 + iw;                 // + (ci)*HWP
        const float* asrc = g_Wre + tap * 65536 + co0 + ca;    // + (ci)*256

        for (int ci0 = 0; ci0 < 256; ci0 += BK) {
            #pragma unroll
            for (int i = 0; i < 8; i++) {
                int k = ka + 2 * i;
                As[k][ca] = asrc[(ci0 + k) * 256];
            }
            #pragma unroll
            for (int i = 0; i < 4; i++) {
                int k = kb + 4 * i;
                Bs[k][pb] = valid ? bsrc[(ci0 + k) * HWP] : 0.f;
            }
            __syncthreads();

            #pragma unroll
            for (int k = 0; k < BK; k++) {
                float4 a0 = *(const float4*)&As[k][tr * 8];
                float4 a1 = *(const float4*)&As[k][tr * 8 + 4];
                float4 b  = *(const float4*)&Bs[k][tc * 4];
                acc[0][0] += a0.x * b.x; acc[0][1] += a0.x * b.y; acc[0][2] += a0.x * b.z; acc[0][3] += a0.x * b.w;
                acc[1][0] += a0.y * b.x; acc[1][1] += a0.y * b.y; acc[1][2] += a0.y * b.z; acc[1][3] += a0.y * b.w;
                acc[2][0] += a0.z * b.x; acc[2][1] += a0.z * b.y; acc[2][2] += a0.z * b.z; acc[2][3] += a0.z * b.w;
                acc[3][0] += a0.w * b.x; acc[3][1] += a0.w * b.y; acc[3][2] += a0.w * b.z; acc[3][3] += a0.w * b.w;
                acc[4][0] += a1.x * b.x; acc[4][1] += a1.x * b.y; acc[4][2] += a1.x * b.z; acc[4][3] += a1.x * b.w;
                acc[5][0] += a1.y * b.x; acc[5][1] += a1.y * b.y; acc[5][2] += a1.y * b.z; acc[5][3] += a1.y * b.w;
                acc[6][0] += a1.z * b.x; acc[6][1] += a1.z * b.y; acc[6][2] += a1.z * b.z; acc[6][3] += a1.z * b.w;
                acc[7][0] += a1.w * b.x; acc[7][1] += a1.w * b.y; acc[7][2] += a1.w * b.z; acc[7][3] += a1.w * b.w;
            }
            __syncthreads();
        }
    }

    // Fused epilogue
    #pragma unroll
    for (int i = 0; i < 8; i++) {
        const int co = co0 + tr * 8 + i;
        const float* xc = xn + co * HWP;
        float* oc = out + (n * 256 + co) * HWP;
        #pragma unroll
        for (int j = 0; j < 4; j++) {
            int p = p0 + tc * 4 + j;
            int h = p / 56;
            int w = p - h * 56;
            int hr = h - 2; if (hr < 0) hr += 56;
            float xv  = xc[p];
            float xrl = xc[hr * 56 + w];
            float t1v = g_t1[(n * 256 + co) * 56 + h];
            float t9v = g_t9[(n * 56 + h) * 56 + w];
            oc[p] = t1v - (t9v * xrl + xv * acc[i][j]);
        }
    }
}

// ---------------------------------------------------------------------------
extern "C" void kernel_launch(void* const* d_in, const int* in_sizes, int n_in,
                              void* d_out, int out_size) {
    const float* x  = (const float*)d_in[0];
    const float* w6 = (const float*)d_in[1];
    const float* w7 = (const float*)d_in[2];
    float* out = (float*)d_out;

    transpose_w_kernel<<<25 * 65536 / 256, 256>>>(w7);
    rowmax_kernel<<<NB * CC * HH / 4, 128>>>(x);
    softmax_kernel<<<dim3(HH, NB), 64>>>(x, w6);
    conv_fused_kernel<<<dim3(HWP / BN, CC / BM, NB), 256>>>(x, out);
}

// round 11
// speedup vs baseline: 3.0905x; 3.0905x over previous
#include <cuda_runtime.h>
#include <cuda_bf16.h>
#include <math.h>
#include <stdint.h>

// Problem constants
#define NB   32
#define CC   256
#define HH   56
#define WW   56
#define HWP  3136      // 56*56
#define CHW  802816    // 256*3136
#define XPAD 512       // guard rows (128B each) at both ends of g_x arrays

// ---------------------------------------------------------------------------
// Device-global scratch (no allocation).
// g_x{h,l}: x as bf16 hi/lo, layout [(n*4+cb)*HWP + q + XPAD] rows of 64 ci,
//           128B rows, 16B chunk ch stored at position ch ^ (q&7).
// g_W{h,l}: weights as [(tap*4+cb)*256 + co] rows of 64 ci, chunk ^ (co&7).
// ---------------------------------------------------------------------------
#define XROWS ((size_t)NB * 4 * HWP + 2 * XPAD)
__device__ __nv_bfloat16 g_xh[XROWS * 64];
__device__ __nv_bfloat16 g_xl[XROWS * 64];
__device__ __nv_bfloat16 g_Wh[25 * 4 * 256 * 64];
__device__ __nv_bfloat16 g_Wl[25 * 4 * 256 * 64];
__device__ float g_t1[NB * CC * HH];      // max over W
__device__ float g_t9[NB * HH * WW];      // softmax weights

// ---------------------------------------------------------------------------
// Helpers
// ---------------------------------------------------------------------------
__device__ __forceinline__ uint32_t smem_u32(const void* p) {
    uint32_t a;
    asm("{ .reg .u64 t; cvta.to.shared.u64 t, %1; cvt.u32.u64 %0, t; }" : "=r"(a) : "l"(p));
    return a;
}

__device__ __forceinline__ void split1(float v, __nv_bfloat16& h, __nv_bfloat16& l) {
    h = __float2bfloat16(v);
    l = __float2bfloat16(v - __bfloat162float(h));
}

__device__ __forceinline__ void split2(float a, float b, uint32_t& hw, uint32_t& lw) {
    __nv_bfloat16 h0, l0, h1, l1;
    split1(a, h0, l0); split1(b, h1, l1);
    hw = (uint32_t)__bfloat16_as_ushort(h0) | ((uint32_t)__bfloat16_as_ushort(h1) << 16);
    lw = (uint32_t)__bfloat16_as_ushort(l0) | ((uint32_t)__bfloat16_as_ushort(l1) << 16);
}

__device__ __forceinline__ void mma16816(float* d, const uint32_t* a, const uint32_t* b) {
    asm volatile("mma.sync.aligned.m16n8k16.row.col.f32.bf16.bf16.f32 "
        "{%0,%1,%2,%3}, {%4,%5,%6,%7}, {%8,%9}, {%0,%1,%2,%3};"
        : "+f"(d[0]), "+f"(d[1]), "+f"(d[2]), "+f"(d[3])
        : "r"(a[0]), "r"(a[1]), "r"(a[2]), "r"(a[3]), "r"(b[0]), "r"(b[1]));
}

#define LDSM4(r, a)                                                              \
    asm volatile("ldmatrix.sync.aligned.m8n8.x4.shared.b16 {%0,%1,%2,%3}, [%4];" \
        : "=r"((r)[0]), "=r"((r)[1]), "=r"((r)[2]), "=r"((r)[3]) : "r"(a))

#define CPA16(d, s) \
    asm volatile("cp.async.cg.shared.global [%0], [%1], 16;" :: "r"(d), "l"(s) : "memory")

#define STS128Z(addr) \
    asm volatile("st.shared.v4.b32 [%0], {%1, %1, %1, %1};" :: "r"(addr), "r"(0u) : "memory")

// ---------------------------------------------------------------------------
// 1) Weight split+relayout
// ---------------------------------------------------------------------------
__global__ void split_w_kernel(const float* __restrict__ w7) {
    int idx = blockIdx.x * 256 + threadIdx.x;   // 25*4*256*64 = 1,638,400 exact
    int cl  = idx & 63;
    int co  = (idx >> 6) & 255;
    int cb  = (idx >> 14) & 3;
    int tap = idx >> 16;
    float v = w7[co * 6400 + (cb * 64 + cl) * 25 + tap];
    __nv_bfloat16 h, l;
    split1(v, h, l);
    int ch = cl >> 3, wi = cl & 7;
    size_t dst = ((size_t)((tap * 4 + cb) * 256 + co)) * 64 + ((ch ^ (co & 7)) << 3) + wi;
    g_Wh[dst] = h; g_Wl[dst] = l;
}

// ---------------------------------------------------------------------------
// 2) x split+transpose: [n][c][p] -> hi/lo rows [(n*4+cb)*HWP + q + XPAD][64ci]
// ---------------------------------------------------------------------------
__global__ void split_x_kernel(const float* __restrict__ x) {
    __shared__ float tile[64][33];
    int n = blockIdx.z, cb = blockIdx.y;
    int q0t = blockIdx.x * 32;
    int tid = threadIdx.x;
    int ln = tid & 31;
    #pragma unroll
    for (int i = 0; i < 8; i++) {
        int cl = (tid >> 5) + i * 8;
        tile[cl][ln] = x[n * CHW + (cb * 64 + cl) * HWP + q0t + ln];
    }
    __syncthreads();
    int ql = tid >> 3, ch = tid & 7;
    int q = q0t + ql;
    int chs = ch ^ (q & 7);
    uint32_t hw[4], lw[4];
    #pragma unroll
    for (int j = 0; j < 4; j++)
        split2(tile[ch * 8 + j * 2][ql], tile[ch * 8 + j * 2 + 1][ql], hw[j], lw[j]);
    size_t r16 = ((size_t)(n * 4 + cb) * HWP + q + XPAD) * 8 + chs;
    ((uint4*)g_xh)[r16] = make_uint4(hw[0], hw[1], hw[2], hw[3]);
    ((uint4*)g_xl)[r16] = make_uint4(lw[0], lw[1], lw[2], lw[3]);
}

// ---------------------------------------------------------------------------
// 3) t1 = max over W
// ---------------------------------------------------------------------------
__global__ void rowmax_kernel(const float* __restrict__ x) {
    int row  = blockIdx.x * 4 + (threadIdx.x >> 5);
    int lane = threadIdx.x & 31;
    const float* xr = x + row * 56;
    float m = xr[lane];
    if (lane < 24) m = fmaxf(m, xr[lane + 32]);
    #pragma unroll
    for (int o = 16; o > 0; o >>= 1)
        m = fmaxf(m, __shfl_xor_sync(0xffffffffu, m, o));
    if (lane == 0) g_t1[row] = m;
}

// ---------------------------------------------------------------------------
// 4) t9 = softmax_w( sum_c tanh(relu(x)) * w6[c] )
// ---------------------------------------------------------------------------
__global__ void softmax_kernel(const float* __restrict__ x,
                               const float* __restrict__ w6) {
    __shared__ float w6s[256];
    __shared__ float red[64];
    int n = blockIdx.y, h = blockIdx.x;
    int t = threadIdx.x;                                // 64 threads
    for (int c = t; c < 256; c += 64) w6s[c] = w6[c];
    __syncthreads();

    float acc = 0.f;
    if (t < 56) {
        const float* xp = x + (n * 256 * 56 + h) * 56 + t;
        #pragma unroll 4
        for (int c = 0; c < 256; c++) {
            float v = xp[c * HWP];
            float r = fmaxf(v, 0.f);
            float th;
            asm("tanh.approx.f32 %0, %1;" : "=f"(th) : "f"(r));
            acc += th * w6s[c];
        }
    }
    red[t] = (t < 56) ? acc : -INFINITY;
    __syncthreads();
    #pragma unroll
    for (int s = 32; s > 0; s >>= 1) {
        if (t < s) red[t] = fmaxf(red[t], red[t + s]);
        __syncthreads();
    }
    float mx = red[0];
    __syncthreads();
    float e = (t < 56) ? expf(acc - mx) : 0.f;
    red[t] = e;
    __syncthreads();
    #pragma unroll
    for (int s = 32; s > 0; s >>= 1) {
        if (t < s) red[t] += red[t + s];
        __syncthreads();
    }
    float inv = 1.0f / red[0];
    if (t < 56) g_t9[(n * 56 + h) * 56 + t] = e * inv;
}

// ---------------------------------------------------------------------------
// 5) Conv via mma.sync implicit GEMM, bf16 split (hh+hl+lh), fused epilogue.
//    CTA: 128 co x 128 px; 8 warps (4x2), warp tile 32x64.
//    SMEM buf b at b*65536: Ah 16K | Al 16K | Bh 16K | Bl 16K.
// ---------------------------------------------------------------------------
#define SMEM_CONV (2 * 65536)

__global__ __launch_bounds__(256, 1)
void conv_hmma_kernel(const float* __restrict__ x, float* __restrict__ out) {
    extern __shared__ __align__(128) char sm[];
    const uint32_t smb = smem_u32(sm);
    const int tid = threadIdx.x, lane = tid & 31, wid = tid >> 5;
    const int n = blockIdx.z, co0 = blockIdx.y * 128, p0 = blockIdx.x * 128;
    const int m0 = (wid & 3) * 32, n0w = (wid >> 2) * 64;

    // ldmatrix per-lane geometry
    const int a_row = ((lane >> 3) & 1) * 8 + (lane & 7);  // tile order m0,m8 | k0,k8
    const int a_ks  = lane >> 4;
    const int b_row = ((lane >> 4) & 1) * 8 + (lane & 7);  // tile order (n0,k0),(n0,k8),(n8,k0),(n8,k8)
    const int b_ks  = (lane >> 3) & 1;
    const int akey  = lane & 7;

    float acc[2][8][4];
    #pragma unroll
    for (int i = 0; i < 2; i++)
        #pragma unroll
        for (int j = 0; j < 8; j++)
            #pragma unroll
            for (int k = 0; k < 4; k++) acc[i][j][k] = 0.f;

    auto issue = [&](int c) {
        int tap = c >> 2, cb = c & 3;
        int dh = (tap / 5) * 3 - 6, dw = (tap % 5) * 3 - 6;
        long long q0 = (long long)p0 + dh * 56 + dw;
        uint32_t dst = smb + (uint32_t)(c & 1) * 65536u + (uint32_t)tid * 64u;
        const char* ash = (const char*)g_Wh + ((size_t)((tap * 4 + cb) * 256 + co0)) * 128 + tid * 64;
        const char* asl = (const char*)g_Wl + ((size_t)((tap * 4 + cb) * 256 + co0)) * 128 + tid * 64;
        const char* bsh = (const char*)g_xh + (size_t)((long long)(n * 4 + cb) * HWP + q0 + XPAD) * 128 + tid * 64;
        const char* bsl = (const char*)g_xl + (size_t)((long long)(n * 4 + cb) * HWP + q0 + XPAD) * 128 + tid * 64;
        #pragma unroll
        for (int j = 0; j < 4; j++) {
            CPA16(dst + j * 16,          ash + j * 16);
            CPA16(dst + 16384u + j * 16, asl + j * 16);
            CPA16(dst + 32768u + j * 16, bsh + j * 16);
            CPA16(dst + 49152u + j * 16, bsl + j * 16);
        }
        asm volatile("cp.async.commit_group;" ::: "memory");
    };

    issue(0);

    for (int c = 0; c < 100; c++) {
        const uint32_t buf = smb + (uint32_t)(c & 1) * 65536u;
        const int tap = c >> 2;
        const int dh = (tap / 5) * 3 - 6, dw = (tap % 5) * 3 - 6;
        const int q0m = ((p0 + dh * 56 + dw) % 8 + 8) & 7;   // (q0 mod 8), non-negative

        if (c + 1 < 100) {
            issue(c + 1);
            asm volatile("cp.async.wait_group 1;" ::: "memory");
        } else {
            asm volatile("cp.async.wait_group 0;" ::: "memory");
        }
        __syncthreads();

        // zero-fix invalid B rows (conv padding + w-wrap + partial last tile)
        {
            int r = tid >> 1, half = tid & 1;
            int p = p0 + r;
            int h = p / 56, w = p - h * 56;
            int ih = h + dh, iw = w + dw;
            bool valid = (p < HWP) && ((unsigned)ih < 56u) && ((unsigned)iw < 56u);
            if (!valid) {
                uint32_t z = buf + 32768u + (uint32_t)r * 128u + (uint32_t)half * 64u;
                #pragma unroll
                for (int j = 0; j < 4; j++) {
                    STS128Z(z + j * 16);
                    STS128Z(z + 16384u + j * 16);
                }
            }
        }
        __syncthreads();

        const int bkey = (q0m + b_row) & 7;   // B swizzle key tracks global q

        #pragma unroll
        for (int ks = 0; ks < 4; ks++) {
            uint32_t ah[2][4], al[2][4], bh[4][4], bl[4][4];
            #pragma unroll
            for (int mi = 0; mi < 2; mi++) {
                uint32_t ad = buf + (uint32_t)((m0 + mi * 16 + a_row) * 128)
                                  + (uint32_t)(((ks * 2 + a_ks) ^ akey) << 4);
                LDSM4(ah[mi], ad);
                LDSM4(al[mi], ad + 16384u);
            }
            #pragma unroll
            for (int nj = 0; nj < 4; nj++) {
                uint32_t bd = buf + 32768u + (uint32_t)((n0w + nj * 16 + b_row) * 128)
                                  + (uint32_t)(((ks * 2 + b_ks) ^ bkey) << 4);
                LDSM4(bh[nj], bd);
                LDSM4(bl[nj], bd + 16384u);
            }
            #pragma unroll
            for (int mi = 0; mi < 2; mi++)
                #pragma unroll
                for (int nj = 0; nj < 4; nj++) {
                    mma16816(acc[mi][nj * 2],     ah[mi], &bh[nj][0]);
                    mma16816(acc[mi][nj * 2 + 1], ah[mi], &bh[nj][2]);
                    mma16816(acc[mi][nj * 2],     ah[mi], &bl[nj][0]);
                    mma16816(acc[mi][nj * 2 + 1], ah[mi], &bl[nj][2]);
                    mma16816(acc[mi][nj * 2],     al[mi], &bh[nj][0]);
                    mma16816(acc[mi][nj * 2 + 1], al[mi], &bh[nj][2]);
                }
        }
        __syncthreads();
    }

    // ---- fused epilogue: out = t1 - (t9*roll(x) + x*t7) ----
    const int er = lane >> 2, ec = (lane & 3) * 2;
    const float* xn = x + n * CHW;
    #pragma unroll
    for (int mi = 0; mi < 2; mi++) {
        #pragma unroll
        for (int rr = 0; rr < 2; rr++) {
            int co = co0 + m0 + mi * 16 + rr * 8 + er;
            const float* xc  = xn + co * HWP;
            const float* t1r = g_t1 + (n * 256 + co) * 56;
            float* oc = out + (n * 256 + co) * HWP;
            #pragma unroll
            for (int ng = 0; ng < 8; ng++) {
                #pragma unroll
                for (int e = 0; e < 2; e++) {
                    int p = p0 + n0w + ng * 8 + ec + e;
                    if (p < HWP) {
                        int h = p / 56, w = p - h * 56;
                        int hr = h - 2; if (hr < 0) hr += 56;
                        float dv  = acc[mi][ng][rr * 2 + e];
                        float xv  = xc[p];
                        float xrl = xc[hr * 56 + w];
                        oc[p] = t1r[h] - (g_t9[n * HWP + p] * xrl + xv * dv);
                    }
                }
            }
        }
    }
}

// ---------------------------------------------------------------------------
extern "C" void kernel_launch(void* const* d_in, const int* in_sizes, int n_in,
                              void* d_out, int out_size) {
    const float* x  = (const float*)d_in[0];
    const float* w6 = (const float*)d_in[1];
    const float* w7 = (const float*)d_in[2];
    float* out = (float*)d_out;

    cudaFuncSetAttribute(conv_hmma_kernel,
                         cudaFuncAttributeMaxDynamicSharedMemorySize, SMEM_CONV);

    split_w_kernel<<<25 * 4 * 256 * 64 / 256, 256>>>(w7);
    split_x_kernel<<<dim3(HWP / 32, 4, NB), 256>>>(x);
    rowmax_kernel<<<NB * CC * HH / 4, 128>>>(x);
    softmax_kernel<<<dim3(HH, NB), 64>>>(x, w6);
    conv_hmma_kernel<<<dim3(25, 2, NB), 256, SMEM_CONV>>>(x, out);
}